// round 9
// baseline (speedup 1.0000x reference)
#include <cuda_runtime.h>

#define NPTS     65536
#define NT       64
#define NS       32
#define NB       64
#define NWARP    16
#define NTHREADS 512
#define NROWS    (NS + 2)                 // 2 pad rows absorb clamped top spill
#define CPYSZ    (NROWS * 32)             // floats per warp copy (1088)
#define SMEM_SZ  (NWARP * CPYSZ * 4)      // 69632 B

#define RADIUS_F 1.1f
#define STEP_F   (2.0f * RADIUS_F / (NS - 1))
#define INVSTEP_F ((float)(NS - 1) / (2.0f * RADIUS_F))
#define HS       (50.0f * STEP_F)         // z/2 step between lin samples (~3.55)

__device__ __forceinline__ float tanh_approx(float x) {
    float r;
    asm("tanh.approx.f32 %0, %1;" : "=f"(r) : "f"(x));
    return r;
}

// Grid (64, 2, 2): (graph, theta-half, node-half). 2 CTAs/SM residency.
// Warp-private smem delta accumulation; per-CTA parallel prefix over s of the
// PARTIAL deltas (prefix is linear), RED-atomic combine into out (pre-zeroed
// by an async memset node).
__global__ void __launch_bounds__(NTHREADS, 2) ect_fused(
    const float* __restrict__ x, const float* __restrict__ v,
    const int* __restrict__ batch, float* __restrict__ out)
{
    extern __shared__ float sacc[];       // [warp][NROWS][32], bank = lane

    const int tid   = threadIdx.x;
    const int w     = tid >> 5;
    const int lane  = tid & 31;
    const int b     = blockIdx.x;         // graph id
    const int tbase = blockIdx.y << 5;    // theta half
    const int t     = tbase + lane;

    #pragma unroll
    for (int i = tid; i < NWARP * CPYSZ; i += NTHREADS) sacc[i] = 0.f;

    // ---- 2-round 512x128 counting search for the graph's [gs, ge) ----
    const int probe = batch[tid * 128 + 127];
    const int c1a = __syncthreads_count(probe < b);
    const int c1b = __syncthreads_count(probe < b + 1);
    const int pa  = (c1a < NTHREADS && tid < 128) ? batch[c1a * 128 + tid] : 0x7fffffff;
    const int c2a = __syncthreads_count(pa < b);
    const int pb  = (c1b < NTHREADS && tid < 128) ? batch[c1b * 128 + tid] : 0x7fffffff;
    const int c2b = __syncthreads_count(pb < b + 1);
    const int gs = (c1a < NTHREADS) ? c1a * 128 + c2a : NPTS;
    const int ge = (c1b < NTHREADS) ? c1b * 128 + c2b : NPTS;

    // this CTA's node half
    const int mid   = gs + ((ge - gs) >> 1);
    const int start = blockIdx.z ? mid : gs;
    const int end   = blockIdx.z ? ge  : mid;

    const float v0 = v[0 * NT + t];
    const float v1 = v[1 * NT + t];
    const float v2 = v[2 * NT + t];

    float* wacc = sacc + w * CPYSZ + lane;

    // ---- main loop: prefetched warp-uniform loads, 4 tanh, 5 unconditional RMW ----
    int n = start + w;
    float x0 = 0.f, x1 = 0.f, x2 = 0.f;
    if (n < end) {
        x0 = __ldg(x + 3 * n + 0);
        x1 = __ldg(x + 3 * n + 1);
        x2 = __ldg(x + 3 * n + 2);
    }
    while (n < end) {
        const int nn = n + NWARP;
        float y0 = 0.f, y1 = 0.f, y2 = 0.f;
        if (nn < end) {
            y0 = __ldg(x + 3 * nn + 0);
            y1 = __ldg(x + 3 * nn + 1);
            y2 = __ldg(x + 3 * nn + 2);
        }

        const float nh = fmaf(x0, v0, fmaf(x1, v1, x2 * v2));
        float fs = floorf((nh + RADIUS_F) * INVSTEP_F);
        fs = fminf(fmaxf(fs, 1.f), 30.f);
        const int s0 = (int)fs;
        // tanh half-arg at s = s0-1:  50*((s0-1)*STEP - R - nh)
        const float a = fmaf(fs, HS, fmaf(-50.0f, nh, -(HS + 50.0f * RADIUS_F)));

        const float g0 = fmaf(0.5f, tanh_approx(a),            0.5f);
        const float g1 = fmaf(0.5f, tanh_approx(a + HS),       0.5f);
        const float g2 = fmaf(0.5f, tanh_approx(a + 2.f * HS), 0.5f);
        const float g3 = fmaf(0.5f, tanh_approx(a + 3.f * HS), 0.5f);

        float* pp = wacc + (s0 - 1) * 32;   // rows s0-1 .. s0+3, all in [0, 33]
        pp[0 * 32] += g0;
        pp[1 * 32] += g1 - g0;
        pp[2 * 32] += g2 - g1;
        pp[3 * 32] += g3 - g2;
        pp[4 * 32] += 1.f - g3;

        x0 = y0; x1 = y1; x2 = y2;
        n = nn;
    }
    __syncthreads();

    // ---- collapse 16 warp copies into region A (offsets [0,1024)) ----
    #pragma unroll
    for (int e = tid; e < NS * 32; e += NTHREADS) {
        float sum = 0.f;
        #pragma unroll
        for (int w2 = 0; w2 < NWARP; w2++)
            sum += sacc[w2 * CPYSZ + e];
        sacc[e] = sum;
    }
    __syncthreads();

    // ---- parallel Hillis-Steele prefix over s (5 steps, ping-pong A<->B) ----
    float* A = sacc;
    float* B = sacc + CPYSZ;              // reuse warp copy 1 region
    #pragma unroll
    for (int d = 1; d < NS; d <<= 1) {
        #pragma unroll
        for (int e = tid; e < NS * 32; e += NTHREADS) {
            const int s = e >> 5;
            float val = A[e];
            if (s >= d) val += A[e - (d << 5)];
            B[e] = val;
        }
        __syncthreads();
        float* tmp = A; A = B; B = tmp;
    }

    // ---- RED-atomic combine of partial prefixes into out ----
    #pragma unroll
    for (int e = tid; e < NS * 32; e += NTHREADS) {
        const int s = e >> 5, l = e & 31;
        atomicAdd(&out[(b * NS + s) * NT + tbase + l], A[e]);
    }
}

extern "C" void kernel_launch(void* const* d_in, const int* in_sizes, int n_in,
                              void* d_out, int out_size) {
    (void)in_sizes; (void)n_in; (void)out_size;
    const float* x     = (const float*)d_in[0];
    const float* v     = (const float*)d_in[1];
    // d_in[2] = lin (reconstructed analytically; matches jnp.linspace to fp rounding)
    const int*   batch = (const int*)d_in[3];
    float* out = (float*)d_out;

    static int smem_set = 0;
    if (!smem_set) {
        cudaFuncSetAttribute(ect_fused, cudaFuncAttributeMaxDynamicSharedMemorySize, SMEM_SZ);
        smem_set = 1;
    }
    cudaMemsetAsync(out, 0, NB * NS * NT * sizeof(float));
    dim3 grid(NB, 2, 2);
    ect_fused<<<grid, NTHREADS, SMEM_SZ>>>(x, v, batch, out);
}

// round 10
// speedup vs baseline: 1.1047x; 1.1047x over previous
#include <cuda_runtime.h>

#define NPTS     65536
#define NT       64
#define NS       32
#define NB       64
#define NWARP    32
#define NTHREADS 1024
#define NROWS    (NS + 1)                  // 1 pad row absorbs clamped top spill
#define CPYSZ    (NROWS * 32)              // floats per warp copy (1056)
#define XSCAP    1344                      // staged node capacity (mean 1024, sd ~32)
#define SMEM_SZ  ((NWARP * CPYSZ + XSCAP * 3) * 4)   // 135168 + 16128 = 151296 B

#define RADIUS_F 1.1f
#define STEP_F   (2.0f * RADIUS_F / (NS - 1))
#define INVSTEP_F ((float)(NS - 1) / (2.0f * RADIUS_F))
#define HS       (50.0f * STEP_F)          // z/2 step between lin samples (~3.55)

__device__ __forceinline__ float tanh_approx(float x) {
    float r;
    asm("tanh.approx.f32 %0, %1;" : "=f"(r) : "f"(x));
    return r;
}

// One CTA per (graph, theta-half), 1024 threads, 32 warp-private smem copies.
// 3-tanh / 4-bucket windowed sigmoid deltas, smem-staged coords, in-CTA
// parallel prefix over s, deterministic direct store. Single launch, no atomics.
__global__ void __launch_bounds__(NTHREADS, 1) ect_fused(
    const float* __restrict__ x, const float* __restrict__ v,
    const int* __restrict__ batch, float* __restrict__ out)
{
    extern __shared__ float smem[];
    float* sacc = smem;                    // [warp][NROWS][32], bank = lane
    float* xs   = smem + NWARP * CPYSZ;    // staged coords [XSCAP][3]

    const int tid   = threadIdx.x;
    const int w     = tid >> 5;
    const int lane  = tid & 31;
    const int b     = blockIdx.x;          // graph id
    const int tbase = blockIdx.y << 5;     // theta half
    const int t     = tbase + lane;

    #pragma unroll
    for (int i = tid; i < NWARP * CPYSZ; i += NTHREADS) sacc[i] = 0.f;

    // ---- 2-round 1024x64 counting search for graph b's [gs, ge) ----
    const int probe = batch[tid * 64 + 63];
    const int c1a = __syncthreads_count(probe < b);
    const int c1b = __syncthreads_count(probe < b + 1);
    const int pa  = (c1a < NTHREADS && tid < 64) ? batch[c1a * 64 + tid] : 0x7fffffff;
    const int c2a = __syncthreads_count(pa < b);
    const int pb  = (c1b < NTHREADS && tid < 64) ? batch[c1b * 64 + tid] : 0x7fffffff;
    const int c2b = __syncthreads_count(pb < b + 1);
    const int gs = (c1a < NTHREADS) ? c1a * 64 + c2a : NPTS;
    const int ge = (c1b < NTHREADS) ? c1b * 64 + c2b : NPTS;
    const int cnt = ge - gs;

    // ---- stage this graph's coords (coalesced) ----
    const int stage = cnt < XSCAP ? cnt : XSCAP;
    for (int i = tid; i < stage * 3; i += NTHREADS) xs[i] = x[gs * 3 + i];
    __syncthreads();

    const float v0 = v[0 * NT + t];
    const float v1 = v[1 * NT + t];
    const float v2 = v[2 * NT + t];

    float* wacc = sacc + w * CPYSZ + lane;

    // ---- main loop: broadcast LDS coords, 3 tanh, 4 unconditional RMW ----
    for (int i = w; i < cnt; i += NWARP) {
        float x0, x1, x2;
        if (i < XSCAP) {
            x0 = xs[3 * i + 0]; x1 = xs[3 * i + 1]; x2 = xs[3 * i + 2];
        } else {                      // overflow fallback (graph > XSCAP nodes)
            const float* p = x + 3 * (gs + i);
            x0 = __ldg(p); x1 = __ldg(p + 1); x2 = __ldg(p + 2);
        }

        const float nh = fmaf(x0, v0, fmaf(x1, v1, x2 * v2));
        float fs = floorf((nh + RADIUS_F) * INVSTEP_F);
        fs = fminf(fmaxf(fs, 1.f), 30.f);
        const int s0 = (int)fs;
        // tanh half-arg at s = s0-1:  50*((s0-1)*STEP - R - nh)
        const float a = fmaf(fs, HS, fmaf(-50.0f, nh, -(HS + 50.0f * RADIUS_F)));

        const float g0 = fmaf(0.5f, tanh_approx(a),            0.5f);
        const float g1 = fmaf(0.5f, tanh_approx(a + HS),       0.5f);
        const float g2 = fmaf(0.5f, tanh_approx(a + 2.f * HS), 0.5f);

        float* pp = wacc + (s0 - 1) * 32;    // rows s0-1 .. s0+2, all in [0, 32]
        pp[0 * 32] += g0;
        pp[1 * 32] += g1 - g0;
        pp[2 * 32] += g2 - g1;
        pp[3 * 32] += 1.f - g2;
    }
    __syncthreads();

    // ---- collapse 32 warp copies; thread tid owns element tid (race-free) ----
    {
        float sum = 0.f;
        #pragma unroll
        for (int w2 = 0; w2 < NWARP; w2++)
            sum += sacc[w2 * CPYSZ + tid];
        sacc[tid] = sum;
    }

    // ---- parallel Hillis-Steele prefix over s (5 steps, ping-pong) ----
    float* A = sacc;
    float* B = sacc + CPYSZ;               // dead warp-copy-1 region
    const int s = tid >> 5;
    #pragma unroll
    for (int d = 1; d < NS; d <<= 1) {
        __syncthreads();
        float val = A[tid];
        if (s >= d) val += A[tid - (d << 5)];
        B[tid] = val;
        float* tmp = A; A = B; B = tmp;
    }
    // each thread reads back the element it just wrote: no final barrier needed
    out[(b * NS + s) * NT + tbase + lane] = A[tid];
}

extern "C" void kernel_launch(void* const* d_in, const int* in_sizes, int n_in,
                              void* d_out, int out_size) {
    (void)in_sizes; (void)n_in; (void)out_size;
    const float* x     = (const float*)d_in[0];
    const float* v     = (const float*)d_in[1];
    // d_in[2] = lin (reconstructed analytically; matches jnp.linspace to fp rounding)
    const int*   batch = (const int*)d_in[3];
    float* out = (float*)d_out;

    static int smem_set = 0;
    if (!smem_set) {
        cudaFuncSetAttribute(ect_fused, cudaFuncAttributeMaxDynamicSharedMemorySize, SMEM_SZ);
        smem_set = 1;
    }
    dim3 grid(NB, 2);
    ect_fused<<<grid, NTHREADS, SMEM_SZ>>>(x, v, batch, out);
}

// round 11
// speedup vs baseline: 1.2548x; 1.1359x over previous
#include <cuda_runtime.h>

#define NPTS     65536
#define NT       64
#define NS       32
#define NB       64
#define NWARP    32
#define NTHREADS 1024
#define NROWS    (NS + 1)                  // 1 pad row absorbs clamped top spill
#define CPYSZ    (NROWS * 32)              // floats per warp copy (1056)
#define XSCAP    1344                      // staged node capacity (mean 1024, sd ~32)
#define SMEM_SZ  (NWARP * CPYSZ * 4 + XSCAP * 16)   // 135168 + 21504 = 156672 B

#define RADIUS_F 1.1f
#define STEP_F   (2.0f * RADIUS_F / (NS - 1))
#define INVSTEP_F ((float)(NS - 1) / (2.0f * RADIUS_F))
#define HS       (50.0f * STEP_F)          // z/2 step between lin samples (~3.55)

__device__ __forceinline__ float tanh_approx(float x) {
    float r;
    asm("tanh.approx.f32 %0, %1;" : "=f"(r) : "f"(x));
    return r;
}

// One CTA per (graph, theta-half), 1024 threads, 32 warp-private smem copies.
// 2-node interleaved main loop (explicit ILP to cover LDS/MUFU latency),
// float4-staged coords (1 broadcast LDS.128 per node), 3-tanh/4-bucket
// windowed sigmoid deltas, in-CTA parallel prefix, direct store. One launch.
__global__ void __launch_bounds__(NTHREADS, 1) ect_fused(
    const float* __restrict__ x, const float* __restrict__ v,
    const int* __restrict__ batch, float* __restrict__ out)
{
    extern __shared__ float smem[];
    float*  sacc = smem;                        // [warp][NROWS][32], bank = lane
    float4* xs4  = (float4*)(smem + NWARP * CPYSZ);  // staged coords [XSCAP]

    const int tid   = threadIdx.x;
    const int w     = tid >> 5;
    const int lane  = tid & 31;
    const int b     = blockIdx.x;               // graph id
    const int tbase = blockIdx.y << 5;          // theta half
    const int t     = tbase + lane;

    #pragma unroll
    for (int i = tid; i < NWARP * CPYSZ; i += NTHREADS) sacc[i] = 0.f;

    // ---- 2-round 1024x64 counting search for graph b's [gs, ge) ----
    const int probe = batch[tid * 64 + 63];
    const int c1a = __syncthreads_count(probe < b);
    const int c1b = __syncthreads_count(probe < b + 1);
    const int pa  = (c1a < NTHREADS && tid < 64) ? batch[c1a * 64 + tid] : 0x7fffffff;
    const int c2a = __syncthreads_count(pa < b);
    const int pb  = (c1b < NTHREADS && tid < 64) ? batch[c1b * 64 + tid] : 0x7fffffff;
    const int c2b = __syncthreads_count(pb < b + 1);
    const int gs = (c1a < NTHREADS) ? c1a * 64 + c2a : NPTS;
    const int ge = (c1b < NTHREADS) ? c1b * 64 + c2b : NPTS;
    const int cnt = ge - gs;

    // ---- stage coords as float4 (pad w) ----
    const int stage = cnt < XSCAP ? cnt : XSCAP;
    for (int i = tid; i < stage; i += NTHREADS) {
        const float* p = x + 3 * (gs + i);
        xs4[i] = make_float4(p[0], p[1], p[2], 0.f);
    }
    __syncthreads();

    const float v0 = v[0 * NT + t];
    const float v1 = v[1 * NT + t];
    const float v2 = v[2 * NT + t];

    float* wacc = sacc + w * CPYSZ + lane;

    // ---- main loop: 2 nodes per iteration (independent chains) ----
    int i = w;
    for (; i + NWARP < stage; i += 2 * NWARP) {
        const float4 pA = xs4[i];
        const float4 pB = xs4[i + NWARP];

        // node A front
        const float nhA = fmaf(pA.x, v0, fmaf(pA.y, v1, pA.z * v2));
        float fsA = floorf((nhA + RADIUS_F) * INVSTEP_F);
        fsA = fminf(fmaxf(fsA, 1.f), 30.f);
        const int s0A = (int)fsA;
        const float aA = fmaf(fsA, HS, fmaf(-50.0f, nhA, -(HS + 50.0f * RADIUS_F)));
        // node B front
        const float nhB = fmaf(pB.x, v0, fmaf(pB.y, v1, pB.z * v2));
        float fsB = floorf((nhB + RADIUS_F) * INVSTEP_F);
        fsB = fminf(fmaxf(fsB, 1.f), 30.f);
        const int s0B = (int)fsB;
        const float aB = fmaf(fsB, HS, fmaf(-50.0f, nhB, -(HS + 50.0f * RADIUS_F)));

        const float gA0 = fmaf(0.5f, tanh_approx(aA),            0.5f);
        const float gA1 = fmaf(0.5f, tanh_approx(aA + HS),       0.5f);
        const float gA2 = fmaf(0.5f, tanh_approx(aA + 2.f * HS), 0.5f);
        const float gB0 = fmaf(0.5f, tanh_approx(aB),            0.5f);
        const float gB1 = fmaf(0.5f, tanh_approx(aB + HS),       0.5f);
        const float gB2 = fmaf(0.5f, tanh_approx(aB + 2.f * HS), 0.5f);

        float* ppA = wacc + (s0A - 1) * 32;     // rows s0A-1 .. s0A+2, in [0, 32]
        ppA[0 * 32] += gA0;
        ppA[1 * 32] += gA1 - gA0;
        ppA[2 * 32] += gA2 - gA1;
        ppA[3 * 32] += 1.f - gA2;

        float* ppB = wacc + (s0B - 1) * 32;
        ppB[0 * 32] += gB0;
        ppB[1 * 32] += gB1 - gB0;
        ppB[2 * 32] += gB2 - gB1;
        ppB[3 * 32] += 1.f - gB2;
    }
    // tail: remaining staged node (at most one per warp) + unstaged overflow
    for (; i < cnt; i += NWARP) {
        float x0, x1, x2;
        if (i < XSCAP) {
            const float4 p = xs4[i];
            x0 = p.x; x1 = p.y; x2 = p.z;
        } else {
            const float* p = x + 3 * (gs + i);
            x0 = __ldg(p); x1 = __ldg(p + 1); x2 = __ldg(p + 2);
        }
        const float nh = fmaf(x0, v0, fmaf(x1, v1, x2 * v2));
        float fs = floorf((nh + RADIUS_F) * INVSTEP_F);
        fs = fminf(fmaxf(fs, 1.f), 30.f);
        const int s0 = (int)fs;
        const float a = fmaf(fs, HS, fmaf(-50.0f, nh, -(HS + 50.0f * RADIUS_F)));
        const float g0 = fmaf(0.5f, tanh_approx(a),            0.5f);
        const float g1 = fmaf(0.5f, tanh_approx(a + HS),       0.5f);
        const float g2 = fmaf(0.5f, tanh_approx(a + 2.f * HS), 0.5f);
        float* pp = wacc + (s0 - 1) * 32;
        pp[0 * 32] += g0;
        pp[1 * 32] += g1 - g0;
        pp[2 * 32] += g2 - g1;
        pp[3 * 32] += 1.f - g2;
    }
    __syncthreads();

    // ---- collapse 32 warp copies; thread tid owns element tid ----
    {
        float sum = 0.f;
        #pragma unroll
        for (int w2 = 0; w2 < NWARP; w2++)
            sum += sacc[w2 * CPYSZ + tid];
        sacc[tid] = sum;
    }

    // ---- parallel Hillis-Steele prefix over s (5 steps, ping-pong) ----
    float* A = sacc;
    float* B = sacc + CPYSZ;                    // dead warp-copy-1 region
    const int s = tid >> 5;
    #pragma unroll
    for (int d = 1; d < NS; d <<= 1) {
        __syncthreads();
        float val = A[tid];
        if (s >= d) val += A[tid - (d << 5)];
        B[tid] = val;
        float* tmp = A; A = B; B = tmp;
    }
    // each thread reads back the element it just wrote: no final barrier needed
    out[(b * NS + s) * NT + tbase + lane] = A[tid];
}

extern "C" void kernel_launch(void* const* d_in, const int* in_sizes, int n_in,
                              void* d_out, int out_size) {
    (void)in_sizes; (void)n_in; (void)out_size;
    const float* x     = (const float*)d_in[0];
    const float* v     = (const float*)d_in[1];
    // d_in[2] = lin (reconstructed analytically; matches jnp.linspace to fp rounding)
    const int*   batch = (const int*)d_in[3];
    float* out = (float*)d_out;

    static int smem_set = 0;
    if (!smem_set) {
        cudaFuncSetAttribute(ect_fused, cudaFuncAttributeMaxDynamicSharedMemorySize, SMEM_SZ);
        smem_set = 1;
    }
    dim3 grid(NB, 2);
    ect_fused<<<grid, NTHREADS, SMEM_SZ>>>(x, v, batch, out);
}

// round 12
// speedup vs baseline: 1.2737x; 1.0151x over previous
#include <cuda_runtime.h>

#define NPTS     65536
#define NT       64
#define NS       32
#define NB       64
#define NWARP    32
#define NTHREADS 1024
#define NROWS    (NS + 1)                  // 1 pad row absorbs clamped top spill
#define CPYSZ    (NROWS * 32)              // floats per warp copy (1056)
#define ACCFLT   (NWARP * CPYSZ)           // 33792 floats
#define XSCAP    1344                      // staged node capacity (mean 1024, sd ~32)
#define SMEM_SZ  (ACCFLT * 4 + XSCAP * 16) // 135168 + 21504 = 156672 B

#define RADIUS_F 1.1f
#define STEP_F   (2.0f * RADIUS_F / (NS - 1))
#define INVSTEP_F ((float)(NS - 1) / (2.0f * RADIUS_F))
#define HS       (50.0f * STEP_F)          // z/2 step between lin samples (~3.55)
#define RINV     (RADIUS_F * INVSTEP_F)
#define ACON     (-(HS + 50.0f * RADIUS_F))

__device__ __forceinline__ float tanh_approx(float x) {
    float r;
    asm("tanh.approx.f32 %0, %1;" : "=f"(r) : "f"(x));
    return r;
}

struct NodeFront {
    int   s0;
    float g0, g1, g2;
};

__device__ __forceinline__ void front(const float4 p, float v0, float v1, float v2,
                                      NodeFront& f) {
    const float nh = fmaf(p.x, v0, fmaf(p.y, v1, p.z * v2));
    int s0 = __float2int_rn(fmaf(nh, INVSTEP_F, RINV));   // round-based window
    s0 = s0 < 1 ? 1 : (s0 > 30 ? 30 : s0);
    const float a = fmaf((float)s0, HS, fmaf(-50.0f, nh, ACON));
    f.s0 = s0;
    f.g0 = fmaf(0.5f, tanh_approx(a),            0.5f);
    f.g1 = fmaf(0.5f, tanh_approx(a + HS),       0.5f);
    f.g2 = fmaf(0.5f, tanh_approx(a + 2.f * HS), 0.5f);
}

__device__ __forceinline__ void scatter(float* wacc, const NodeFront& f) {
    float* pp = wacc + (f.s0 - 1) * 32;    // rows s0-1 .. s0+2, all in [0, 32]
    pp[0 * 32] += f.g0;
    pp[1 * 32] += f.g1 - f.g0;
    pp[2 * 32] += f.g2 - f.g1;
    pp[3 * 32] += 1.f - f.g2;
}

// One CTA per (graph, theta-half), 1024 threads, 32 warp-private smem copies.
// 4-node interleaved main loop (32 indep chains/SMSP), round-based 3-tanh/
// 4-bucket windowed sigmoid deltas, float4-staged coords, in-CTA prefix,
// direct store. Single launch, no atomics, no scratch globals.
__global__ void __launch_bounds__(NTHREADS, 1) ect_fused(
    const float* __restrict__ x, const float* __restrict__ v,
    const int* __restrict__ batch, float* __restrict__ out)
{
    extern __shared__ float smem[];
    float*  sacc = smem;                        // [warp][NROWS][32], bank = lane
    float4* xs4  = (float4*)(smem + ACCFLT);    // staged coords [XSCAP]

    const int tid   = threadIdx.x;
    const int w     = tid >> 5;
    const int lane  = tid & 31;
    const int b     = blockIdx.x;               // graph id
    const int tbase = blockIdx.y << 5;          // theta half
    const int t     = tbase + lane;

    // zero accumulator with STS.128
    {
        float4* z = (float4*)sacc;
        #pragma unroll
        for (int i = tid; i < ACCFLT / 4; i += NTHREADS)
            z[i] = make_float4(0.f, 0.f, 0.f, 0.f);
    }

    // ---- 2-round 1024x64 counting search for graph b's [gs, ge) ----
    const int probe = batch[tid * 64 + 63];
    const int c1a = __syncthreads_count(probe < b);
    const int c1b = __syncthreads_count(probe < b + 1);
    const int pa  = (c1a < NTHREADS && tid < 64) ? batch[c1a * 64 + tid] : 0x7fffffff;
    const int c2a = __syncthreads_count(pa < b);
    const int pb  = (c1b < NTHREADS && tid < 64) ? batch[c1b * 64 + tid] : 0x7fffffff;
    const int c2b = __syncthreads_count(pb < b + 1);
    const int gs = (c1a < NTHREADS) ? c1a * 64 + c2a : NPTS;
    const int ge = (c1b < NTHREADS) ? c1b * 64 + c2b : NPTS;
    const int cnt = ge - gs;

    // ---- stage coords as float4 ----
    const int stage = cnt < XSCAP ? cnt : XSCAP;
    for (int i = tid; i < stage; i += NTHREADS) {
        const float* p = x + 3 * (gs + i);
        xs4[i] = make_float4(p[0], p[1], p[2], 0.f);
    }
    __syncthreads();

    const float v0 = v[0 * NT + t];
    const float v1 = v[1 * NT + t];
    const float v2 = v[2 * NT + t];

    float* wacc = sacc + w * CPYSZ + lane;

    // ---- main loop: 4 nodes per iteration, phase-batched ----
    int i = w;
    for (; i + 3 * NWARP < stage; i += 4 * NWARP) {
        const float4 pA = xs4[i];
        const float4 pB = xs4[i + NWARP];
        const float4 pC = xs4[i + 2 * NWARP];
        const float4 pD = xs4[i + 3 * NWARP];

        NodeFront fA, fB, fC, fD;
        front(pA, v0, v1, v2, fA);
        front(pB, v0, v1, v2, fB);
        front(pC, v0, v1, v2, fC);
        front(pD, v0, v1, v2, fD);

        scatter(wacc, fA);
        scatter(wacc, fB);
        scatter(wacc, fC);
        scatter(wacc, fD);
    }
    // tail: remaining staged nodes + unstaged overflow
    for (; i < cnt; i += NWARP) {
        float4 p;
        if (i < XSCAP) {
            p = xs4[i];
        } else {
            const float* q = x + 3 * (gs + i);
            p = make_float4(__ldg(q), __ldg(q + 1), __ldg(q + 2), 0.f);
        }
        NodeFront f;
        front(p, v0, v1, v2, f);
        scatter(wacc, f);
    }
    __syncthreads();

    // ---- collapse 32 warp copies; thread tid owns element tid (race-free) ----
    {
        float sum = 0.f;
        #pragma unroll
        for (int w2 = 0; w2 < NWARP; w2++)
            sum += sacc[w2 * CPYSZ + tid];
        sacc[tid] = sum;
    }

    // ---- parallel Hillis-Steele prefix over s (5 steps, ping-pong) ----
    float* A = sacc;
    float* B = sacc + CPYSZ;                    // dead warp-copy-1 region
    const int s = tid >> 5;
    #pragma unroll
    for (int d = 1; d < NS; d <<= 1) {
        __syncthreads();
        float val = A[tid];
        if (s >= d) val += A[tid - (d << 5)];
        B[tid] = val;
        float* tmp = A; A = B; B = tmp;
    }
    // each thread reads back the element it just wrote: no final barrier needed
    out[(b * NS + s) * NT + tbase + lane] = A[tid];
}

extern "C" void kernel_launch(void* const* d_in, const int* in_sizes, int n_in,
                              void* d_out, int out_size) {
    (void)in_sizes; (void)n_in; (void)out_size;
    const float* x     = (const float*)d_in[0];
    const float* v     = (const float*)d_in[1];
    // d_in[2] = lin (reconstructed analytically; matches jnp.linspace to fp rounding)
    const int*   batch = (const int*)d_in[3];
    float* out = (float*)d_out;

    static int smem_set = 0;
    if (!smem_set) {
        cudaFuncSetAttribute(ect_fused, cudaFuncAttributeMaxDynamicSharedMemorySize, SMEM_SZ);
        smem_set = 1;
    }
    dim3 grid(NB, 2);
    ect_fused<<<grid, NTHREADS, SMEM_SZ>>>(x, v, batch, out);
}